// round 13
// baseline (speedup 1.0000x reference)
#include <cuda_runtime.h>
#include <cuda_fp16.h>
#include <stdint.h>

static constexpr int kN = 50000;
static constexpr int kE = 600000;
static constexpr int kM = 128;
static constexpr int kNCRYS = 256;

static constexpr size_t OFF_VI   = (size_t)kE * kM;
static constexpr size_t OFF_GLOB = OFF_VI + (size_t)kN * kM;
static constexpr size_t OFF_ANF  = OFF_GLOB + (size_t)kNCRYS * 256;

// ---------------- scratch ----------------------------------------------------
__device__ float g_rho[(size_t)kN * kM];
__device__ float g_eksum[(size_t)kN * kM];
__device__ float g_viraw[(size_t)kN * kM];
__device__ float g_bnsum[kM];
__device__ float g_bnsumsq[kM];
__device__ __half g_atom_fp16[(size_t)kN * kM];  // atom pre-rounded to fp16
__device__ uint32_t g_Wfrag16[9 * 8192];         // fp16 frag-major weights
__device__ float g_P1[(size_t)kN * kM];          // atom @ We1[0:128]
__device__ float g_P2[(size_t)kN * kM];          // atom @ We1[128:256]
__device__ float g_Pv[(size_t)kN * kM];          // atom @ Wv1[0:128]

// ---------------- helpers -----------------------------------------------------
__device__ __forceinline__ uint32_t smem_u32(const void* p) {
  uint32_t a;
  asm("{ .reg .u64 t; cvta.to.shared.u64 t, %1; cvt.u32.u64 %0, t; }" : "=r"(a) : "l"(p));
  return a;
}
__device__ __forceinline__ float lrelu(float v) { return v >= 0.f ? v : 0.2f * v; }
__device__ __forceinline__ void red2(float* p, float x, float y) {
  asm volatile("red.global.add.v2.f32 [%0], {%1,%2};" :: "l"(p), "f"(x), "f"(y) : "memory");
}
__device__ __forceinline__ void red4(float* p, float4 v) {
  asm volatile("red.global.add.v4.f32 [%0], {%1,%2,%3,%4};"
               :: "l"(p), "f"(v.x), "f"(v.y), "f"(v.z), "f"(v.w) : "memory");
}
__device__ __forceinline__ void cpa16(uint32_t dst, const void* src) {
  asm volatile("cp.async.cg.shared.global [%0], [%1], 16;" :: "r"(dst), "l"(src));
}
#define CP_COMMIT() asm volatile("cp.async.commit_group;")
#define CP_WAIT0()  asm volatile("cp.async.wait_group 0;")

__device__ __forceinline__ uint32_t pack_h2(float a, float b) {
  __half2 h = __floats2half2_rn(a, b);
  return *reinterpret_cast<uint32_t*>(&h);
}

__device__ __forceinline__ void mma16(float* c, const uint32_t* a, uint32_t b0, uint32_t b1) {
  asm volatile(
      "mma.sync.aligned.m16n8k16.row.col.f32.f16.f16.f32 "
      "{%0,%1,%2,%3}, {%4,%5,%6,%7}, {%8,%9}, {%0,%1,%2,%3};\n"
      : "+f"(c[0]), "+f"(c[1]), "+f"(c[2]), "+f"(c[3])
      : "r"(a[0]), "r"(a[1]), "r"(a[2]), "r"(a[3]), "r"(b0), "r"(b1));
}
__device__ __forceinline__ void ldsm4(uint32_t* a, uint32_t addr) {
  asm volatile("ldmatrix.sync.aligned.m8n8.x4.shared.b16 {%0,%1,%2,%3}, [%4];"
               : "=r"(a[0]), "=r"(a[1]), "=r"(a[2]), "=r"(a[3]) : "r"(addr));
}

// A tile: 128 rows x 136 halves (272 B/row)
static constexpr int AS_RBYTES = 272;
static constexpr int AS_BYTES  = 128 * AS_RBYTES;  // 34816

__device__ __forceinline__ void zero_acc(float acc[4][4][4]) {
#pragma unroll
  for (int a = 0; a < 4; a++)
#pragma unroll
    for (int b = 0; b < 4; b++)
#pragma unroll
      for (int c = 0; c < 4; c++) acc[a][b][c] = 0.f;
}

// 128x128x128 fp16 chunk: acc += As @ Wchunk (B frags straight from gmem, L1-hit).
__device__ __forceinline__ void gemm16(uint32_t as_addr, const uint32_t* __restrict__ Wg,
                                       float acc[4][4][4]) {
  const int lane = threadIdx.x & 31, warp = threadIdx.x >> 5;
  const int wm = warp >> 2, wn = warp & 3;
  const uint2* wb_base = reinterpret_cast<const uint2*>(Wg) + (wn * 4) * 32 + lane;
  const uint32_t abase = as_addr + (uint32_t)((wm * 64 + (lane & 15)) * AS_RBYTES + (lane >> 4) * 16);
#pragma unroll
  for (int ks = 0; ks < 8; ks++) {
    uint32_t a[4][4];
#pragma unroll
    for (int mt = 0; mt < 4; mt++) ldsm4(a[mt], abase + mt * 16 * AS_RBYTES + ks * 32);
    const uint2* wb = wb_base + ks * 512;
#pragma unroll
    for (int nt = 0; nt < 4; nt++) {
      uint2 b = __ldg(wb + nt * 32);
#pragma unroll
      for (int mt = 0; mt < 4; mt++) mma16(acc[mt][nt], a[mt], b.x, b.y);
    }
  }
}

// acc + bias -> lrelu -> fp16 -> As (next layer's A operand).
__device__ __forceinline__ void write_H16(float acc[4][4][4], const float* __restrict__ bias,
                                          char* __restrict__ smem) {
  const int lane = threadIdx.x & 31, warp = threadIdx.x >> 5;
  const int wm = warp >> 2, wn = warp & 3;
  const int g = lane >> 2, t = lane & 3;
#pragma unroll
  for (int nt = 0; nt < 4; nt++) {
    int col0 = wn * 32 + nt * 8 + 2 * t;
    float b0 = bias[col0], b1 = bias[col0 + 1];
#pragma unroll
    for (int mt = 0; mt < 4; mt++) {
      int r0 = wm * 64 + mt * 16 + g;
      *reinterpret_cast<uint32_t*>(smem + r0 * AS_RBYTES + col0 * 2) =
          pack_h2(lrelu(acc[mt][nt][0] + b0), lrelu(acc[mt][nt][1] + b1));
      *reinterpret_cast<uint32_t*>(smem + (r0 + 8) * AS_RBYTES + col0 * 2) =
          pack_h2(lrelu(acc[mt][nt][2] + b0), lrelu(acc[mt][nt][3] + b1));
    }
  }
}

// acc (no bias/act) -> fp32 P rows.
__device__ __forceinline__ void write_P(float acc[4][4][4], float* __restrict__ P, int n0) {
  const int lane = threadIdx.x & 31, warp = threadIdx.x >> 5;
  const int wm = warp >> 2, wn = warp & 3;
  const int g = lane >> 2, t = lane & 3;
#pragma unroll
  for (int nt = 0; nt < 4; nt++) {
    int col0 = wn * 32 + nt * 8 + 2 * t;
#pragma unroll
    for (int mt = 0; mt < 4; mt++) {
#pragma unroll
      for (int h = 0; h < 2; h++) {
        int r = wm * 64 + mt * 16 + g + h * 8;
        if (n0 + r < kN)
          *reinterpret_cast<float2*>(P + (size_t)(n0 + r) * kM + col0) =
              make_float2(acc[mt][nt][2 * h], acc[mt][nt][2 * h + 1]);
      }
    }
  }
}

// fp32 gmem rows -> fp16 smem (cvt path), row clamped.
__device__ __forceinline__ void stage_cvt16(const float* __restrict__ base, int r0,
                                            int rmax, char* __restrict__ smem) {
  int t = threadIdx.x, row = t >> 1, half = t & 1;
  int rsrc = min(r0 + row, rmax - 1);
  const float* src = base + (size_t)rsrc * kM + half * 64;
  char* dst = smem + row * AS_RBYTES + half * 128;
#pragma unroll
  for (int q = 0; q < 8; q++) {
    float4 x = *reinterpret_cast<const float4*>(src + q * 8);
    float4 y = *reinterpret_cast<const float4*>(src + q * 8 + 4);
    *reinterpret_cast<uint4*>(dst + q * 16) =
        make_uint4(pack_h2(x.x, x.y), pack_h2(x.z, x.w), pack_h2(y.x, y.y), pack_h2(y.z, y.w));
  }
}

// ---------------- kernel 1: setup --------------------------------------------
__global__ void setup_kernel(const float* __restrict__ atom,
                             const float* __restrict__ We1, const float* __restrict__ We2,
                             const float* __restrict__ We3,
                             const float* __restrict__ Wv1, const float* __restrict__ Wv2,
                             const float* __restrict__ Wv3,
                             float* __restrict__ out_glob) {
  int i = blockIdx.x * 256 + threadIdx.x;
  if (i < 1600000) {  // 6.4M floats as float4
    float4 z = make_float4(0.f, 0.f, 0.f, 0.f);
    reinterpret_cast<float4*>(g_rho)[i] = z;
    reinterpret_cast<float4*>(g_eksum)[i] = z;
    float4 a = reinterpret_cast<const float4*>(atom)[i];
    reinterpret_cast<uint2*>(g_atom_fp16)[i] =
        make_uint2(pack_h2(a.x, a.y), pack_h2(a.z, a.w));
  }
  if (i < 16384) reinterpret_cast<float4*>(out_glob)[i] = make_float4(0.f, 0.f, 0.f, 0.f);
  if (i < 32) {
    reinterpret_cast<float4*>(g_bnsum)[i] = make_float4(0.f, 0.f, 0.f, 0.f);
    reinterpret_cast<float4*>(g_bnsumsq)[i] = make_float4(0.f, 0.f, 0.f, 0.f);
  }
  if (i < 9 * 8192) {  // fp16 frag-major W images
    int c = i >> 13, r = i & 8191;
    int q = r & 1, l = (r >> 1) & 31, ntg = (r >> 6) & 15, ks = r >> 10;
    const float* Wc;
    if (c < 3)       Wc = We1 + c * 16384;
    else if (c == 3) Wc = We2;
    else if (c == 4) Wc = We3;
    else if (c < 7)  Wc = Wv1 + (c - 5) * 16384;
    else if (c == 7) Wc = Wv2;
    else             Wc = Wv3;
    int n = ntg * 8 + (l >> 2);
    int k0 = ks * 16 + 2 * (l & 3) + (q ? 8 : 0);
    g_Wfrag16[c * 8192 + r] = pack_h2(Wc[k0 * 128 + n], Wc[(k0 + 1) * 128 + n]);
  }
}

// ---------------- kernel 2: precompute P1/P2/Pv (one A stage, 3 GEMMs) --------
__global__ __launch_bounds__(256, 2) void pre_kernel() {
  extern __shared__ char smem[];
  const uint32_t as_addr = smem_u32(smem);
  const int tid = threadIdx.x;
  const int n0 = blockIdx.x * 128;

  // stage contiguous atom rows (fp16, cp.async), clamp last block
  {
    int row = tid >> 1, half = tid & 1;
    int rsrc = min(n0 + row, kN - 1);
    const __half* src = g_atom_fp16 + (size_t)rsrc * kM + half * 64;
    uint32_t dst = as_addr + (uint32_t)(row * AS_RBYTES + half * 128);
#pragma unroll
    for (int q = 0; q < 8; q++) cpa16(dst + q * 16, src + q * 8);
    CP_COMMIT(); CP_WAIT0();
  }
  __syncthreads();

  float acc[4][4][4];
  zero_acc(acc);
  gemm16(as_addr, g_Wfrag16, acc);            // We1 rows [0:128)   -> P1
  write_P(acc, g_P1, n0);
  zero_acc(acc);
  gemm16(as_addr, g_Wfrag16 + 8192, acc);     // We1 rows [128:256) -> P2
  write_P(acc, g_P2, n0);
  zero_acc(acc);
  gemm16(as_addr, g_Wfrag16 + 5 * 8192, acc); // Wv1 rows [0:128)   -> Pv
  write_P(acc, g_Pv, n0);
}

// ---------------- edge SMEM layout -------------------------------------------
static constexpr int SM_IDX1 = AS_BYTES;          // 34816
static constexpr int SM_IDX2 = SM_IDX1 + 512;
static constexpr int SM_INV  = SM_IDX2 + 512;
static constexpr int SM_BIAS = SM_INV + 512;      // 384 floats
static constexpr int EDGE_SMEM = SM_BIAS + 1536;  // 37888

// ---------------- kernel 3: edge MLP (3 GEMMs; layer1 a-parts from P) ---------
__global__ __launch_bounds__(256, 2) void edge_kernel(
    const float* __restrict__ nbr_fea, const float* __restrict__ num_nbrs,
    const int* __restrict__ idx1, const int* __restrict__ idx2,
    const float* __restrict__ be1, const float* __restrict__ be2,
    const float* __restrict__ be3, float* __restrict__ out_ek) {
  extern __shared__ char smem[];
  const uint32_t as_addr = smem_u32(smem);
  int* sidx1 = (int*)(smem + SM_IDX1);
  int* sidx2 = (int*)(smem + SM_IDX2);
  float* sinv = (float*)(smem + SM_INV);
  float* sbias = (float*)(smem + SM_BIAS);
  const int tid = threadIdx.x;
  const int e0 = blockIdx.x * 128;

  if (tid < 128) {
    int e = e0 + tid;
    int i1 = 0, i2 = 0;
    float inv = 0.f;
    if (e < kE) { i1 = idx1[e]; i2 = idx2[e]; inv = 1.f / num_nbrs[i1]; }
    sidx1[tid] = i1; sidx2[tid] = i2; sinv[tid] = inv;
    sbias[tid] = be1[tid]; sbias[128 + tid] = be2[tid]; sbias[256 + tid] = be3[tid];
  }
  __syncthreads();

  // stage nbr chunk into A tile
  stage_cvt16(nbr_fea, e0, kE, smem);

  const int lane = tid & 31, warp = tid >> 5;
  const int wm = warp >> 2, wn = warp & 3;
  const int g = lane >> 2, t = lane & 3;

  // acc init = P1[idx1] + P2[idx2] (L2-resident gathers, fragment layout)
  float acc[4][4][4];
#pragma unroll
  for (int mt = 0; mt < 4; mt++) {
#pragma unroll
    for (int h = 0; h < 2; h++) {
      int row = wm * 64 + mt * 16 + g + h * 8;
      const float* p1 = g_P1 + (size_t)sidx1[row] * kM;
      const float* p2 = g_P2 + (size_t)sidx2[row] * kM;
#pragma unroll
      for (int nt = 0; nt < 4; nt++) {
        int col0 = wn * 32 + nt * 8 + 2 * t;
        float2 u = __ldg(reinterpret_cast<const float2*>(p1 + col0));
        float2 v = __ldg(reinterpret_cast<const float2*>(p2 + col0));
        acc[mt][nt][2 * h]     = u.x + v.x;
        acc[mt][nt][2 * h + 1] = u.y + v.y;
      }
    }
  }
  __syncthreads();  // nbr tile staged

  // layer 1 (nbr part), accumulate onto P-init
  gemm16(as_addr, g_Wfrag16 + 2 * 8192, acc);
  __syncthreads();

  // layer 2
  write_H16(acc, sbias, smem);
  __syncthreads();
  zero_acc(acc);
  gemm16(as_addr, g_Wfrag16 + 3 * 8192, acc);
  __syncthreads();

  // layer 3
  write_H16(acc, sbias + 128, smem);
  __syncthreads();
  zero_acc(acc);
  gemm16(as_addr, g_Wfrag16 + 4 * 8192, acc);

  // Epilogue (R10 proven form): ek = nbr + ek_raw; red2 into rho/eksum.
#pragma unroll
  for (int mt = 0; mt < 4; mt++) {
#pragma unroll
    for (int h = 0; h < 2; h++) {
      int row = wm * 64 + mt * 16 + g + h * 8;
      int e = e0 + row;
      if (e < kE) {
        float inv = sinv[row];
        size_t nbase = (size_t)sidx1[row] * kM;
        const float* nrow = nbr_fea + (size_t)e * kM;
        float* eko = out_ek + (size_t)e * kM;
#pragma unroll
        for (int nt = 0; nt < 4; nt++) {
          int col0 = wn * 32 + nt * 8 + 2 * t;
          float ek0 = acc[mt][nt][2 * h]     + sbias[256 + col0];
          float ek1 = acc[mt][nt][2 * h + 1] + sbias[256 + col0 + 1];
          float2 nb = *reinterpret_cast<const float2*>(nrow + col0);
          float o0 = ek0 + nb.x, o1 = ek1 + nb.y;
          *reinterpret_cast<float2*>(eko + col0) = make_float2(o0, o1);
          red2(g_rho + nbase + col0, ek0 * inv, ek1 * inv);
          red2(g_eksum + nbase + col0, o0 * inv, o1 * inv);
        }
      }
    }
  }
}

// ---------------- kernel 4: node MLP (3 GEMMs; atom part from Pv) -------------
__global__ __launch_bounds__(256, 2) void node_kernel(
    const float* __restrict__ bv1, const float* __restrict__ bv2,
    const float* __restrict__ bv3) {
  extern __shared__ char smem[];
  const uint32_t as_addr = smem_u32(smem);
  const int tid = threadIdx.x;
  const int n0 = blockIdx.x * 128;

  // stage rho chunk
  stage_cvt16(g_rho, n0, kN, smem);

  const int lane = tid & 31, warp = tid >> 5;
  const int wm = warp >> 2, wn = warp & 3;
  const int g = lane >> 2, t = lane & 3;

  // acc init = Pv rows (contiguous)
  float acc[4][4][4];
#pragma unroll
  for (int mt = 0; mt < 4; mt++) {
#pragma unroll
    for (int h = 0; h < 2; h++) {
      int row = wm * 64 + mt * 16 + g + h * 8;
      const float* pv = g_Pv + (size_t)min(n0 + row, kN - 1) * kM;
#pragma unroll
      for (int nt = 0; nt < 4; nt++) {
        int col0 = wn * 32 + nt * 8 + 2 * t;
        float2 u = __ldg(reinterpret_cast<const float2*>(pv + col0));
        acc[mt][nt][2 * h]     = u.x;
        acc[mt][nt][2 * h + 1] = u.y;
      }
    }
  }
  __syncthreads();

  gemm16(as_addr, g_Wfrag16 + 6 * 8192, acc);  // rho part
  __syncthreads();

  write_H16(acc, bv1, smem);
  __syncthreads();
  zero_acc(acc);
  gemm16(as_addr, g_Wfrag16 + 7 * 8192, acc);
  __syncthreads();

  write_H16(acc, bv2, smem);
  __syncthreads();
  zero_acc(acc);
  gemm16(as_addr, g_Wfrag16 + 8 * 8192, acc);

  // Epilogue: vi_raw -> gmem + BN partials (warp shfl-reduce, red2).
#pragma unroll
  for (int nt = 0; nt < 4; nt++) {
    int col0 = wn * 32 + nt * 8 + 2 * t;
    float b0 = bv3[col0], b1 = bv3[col0 + 1];
    float s0 = 0.f, s1 = 0.f, q0 = 0.f, q1 = 0.f;
#pragma unroll
    for (int mt = 0; mt < 4; mt++) {
#pragma unroll
      for (int h = 0; h < 2; h++) {
        int r = wm * 64 + mt * 16 + g + h * 8;
        float v0 = acc[mt][nt][2 * h] + b0;
        float v1 = acc[mt][nt][2 * h + 1] + b1;
        if (n0 + r < kN) {
          *reinterpret_cast<float2*>(g_viraw + (size_t)(n0 + r) * kM + col0) =
              make_float2(v0, v1);
          s0 += v0; s1 += v1;
          q0 += v0 * v0; q1 += v1 * v1;
        }
      }
    }
#pragma unroll
    for (int o = 4; o < 32; o <<= 1) {
      s0 += __shfl_xor_sync(0xFFFFFFFF, s0, o);
      s1 += __shfl_xor_sync(0xFFFFFFFF, s1, o);
      q0 += __shfl_xor_sync(0xFFFFFFFF, q0, o);
      q1 += __shfl_xor_sync(0xFFFFFFFF, q1, o);
    }
    if (lane < 4) {
      red2(g_bnsum + col0, s0, s1);
      red2(g_bnsumsq + col0, q0, q1);
    }
  }
}

// ---------------- kernel 5: apply (BN finalize folded in) ---------------------
__global__ __launch_bounds__(256) void apply_kernel(
    const float* __restrict__ atom, const int* __restrict__ crys,
    const float* __restrict__ gamma, const float* __restrict__ beta,
    float* __restrict__ out_vi, float* __restrict__ out_glob,
    float* __restrict__ out_anf) {
  __shared__ float ssc[kM], ssh[kM];
  if (threadIdx.x < kM) {
    int t = threadIdx.x;
    float mu = g_bnsum[t] * (1.f / (float)kN);
    float var = g_bnsumsq[t] * (1.f / (float)kN) - mu * mu;
    float sc = gamma[t] * rsqrtf(var + 1e-5f);
    ssc[t] = sc;
    ssh[t] = beta[t] - mu * sc;
  }
  __syncthreads();
  int i = blockIdx.x * blockDim.x + threadIdx.x;
  if (i >= kN * 32) return;
  int n = i >> 5, j0 = (i & 31) << 2;
  float4 a = *reinterpret_cast<const float4*>(atom + (size_t)n * kM + j0);
  float4 vr = *reinterpret_cast<const float4*>(g_viraw + (size_t)n * kM + j0);
  float4 v;
  v.x = a.x + vr.x * ssc[j0] + ssh[j0];
  v.y = a.y + vr.y * ssc[j0 + 1] + ssh[j0 + 1];
  v.z = a.z + vr.z * ssc[j0 + 2] + ssh[j0 + 2];
  v.w = a.w + vr.w * ssc[j0 + 3] + ssh[j0 + 3];
  float4 ekv = *reinterpret_cast<const float4*>(g_eksum + (size_t)n * kM + j0);

  *reinterpret_cast<float4*>(out_vi + (size_t)n * kM + j0) = v;
  *reinterpret_cast<float4*>(out_anf + (size_t)n * 256 + j0) = v;
  *reinterpret_cast<float4*>(out_anf + (size_t)n * 256 + 128 + j0) = ekv;
  int cr = crys[n];
  red4(out_glob + (size_t)cr * 256 + j0, v);
  red4(out_glob + (size_t)cr * 256 + 128 + j0, ekv);
}

// ---------------- launcher ----------------------------------------------------
extern "C" void kernel_launch(void* const* d_in, const int* in_sizes, int n_in,
                              void* d_out, int out_size) {
  const float* atom     = (const float*)d_in[0];
  const float* nbr_fea  = (const float*)d_in[1];
  const float* num_nbrs = (const float*)d_in[2];
  const int*   idx1     = (const int*)d_in[3];
  const int*   idx2     = (const int*)d_in[4];
  const int*   crys     = (const int*)d_in[5];
  const float* We1 = (const float*)d_in[6];
  const float* be1 = (const float*)d_in[7];
  const float* We2 = (const float*)d_in[8];
  const float* be2 = (const float*)d_in[9];
  const float* We3 = (const float*)d_in[10];
  const float* be3 = (const float*)d_in[11];
  const float* Wv1 = (const float*)d_in[12];
  const float* bv1 = (const float*)d_in[13];
  const float* Wv2 = (const float*)d_in[14];
  const float* bv2 = (const float*)d_in[15];
  const float* Wv3 = (const float*)d_in[16];
  const float* bv3 = (const float*)d_in[17];
  const float* bn_gamma = (const float*)d_in[18];
  const float* bn_beta  = (const float*)d_in[19];

  float* out = (float*)d_out;
  float* out_ek   = out;
  float* out_vi   = out + OFF_VI;
  float* out_glob = out + OFF_GLOB;
  float* out_anf  = out + OFF_ANF;

  cudaFuncSetAttribute(pre_kernel, cudaFuncAttributeMaxDynamicSharedMemorySize, EDGE_SMEM);
  cudaFuncSetAttribute(edge_kernel, cudaFuncAttributeMaxDynamicSharedMemorySize, EDGE_SMEM);
  cudaFuncSetAttribute(node_kernel, cudaFuncAttributeMaxDynamicSharedMemorySize, EDGE_SMEM);

  setup_kernel<<<6250, 256>>>(atom, We1, We2, We3, Wv1, Wv2, Wv3, out_glob);
  pre_kernel<<<(kN + 127) / 128, 256, EDGE_SMEM>>>();
  edge_kernel<<<(kE + 127) / 128, 256, EDGE_SMEM>>>(
      nbr_fea, num_nbrs, idx1, idx2, be1, be2, be3, out_ek);
  node_kernel<<<(kN + 127) / 128, 256, EDGE_SMEM>>>(bv1, bv2, bv3);
  apply_kernel<<<(kN * 32 + 255) / 256, 256>>>(
      atom, crys, bn_gamma, bn_beta, out_vi, out_glob, out_anf);
}

// round 15
// speedup vs baseline: 1.4248x; 1.4248x over previous
#include <cuda_runtime.h>
#include <cuda_fp16.h>
#include <stdint.h>

static constexpr int kN = 50000;
static constexpr int kE = 600000;
static constexpr int kM = 128;
static constexpr int kNCRYS = 256;

static constexpr size_t OFF_VI   = (size_t)kE * kM;
static constexpr size_t OFF_GLOB = OFF_VI + (size_t)kN * kM;
static constexpr size_t OFF_ANF  = OFF_GLOB + (size_t)kNCRYS * 256;

// ---------------- scratch ----------------------------------------------------
__device__ float g_rho[(size_t)kN * kM];
__device__ float g_eksum[(size_t)kN * kM];
__device__ float g_viraw[(size_t)kN * kM];
__device__ float g_bnsum[kM];
__device__ float g_bnsumsq[kM];
__device__ __half g_atom_fp16[(size_t)kN * kM];  // atom pre-rounded to fp16
__device__ uint32_t g_Wfrag16[9 * 8192];         // fp16 frag-major weights: 5 edge + 4 node

// ---------------- helpers -----------------------------------------------------
__device__ __forceinline__ uint32_t smem_u32(const void* p) {
  uint32_t a;
  asm("{ .reg .u64 t; cvta.to.shared.u64 t, %1; cvt.u32.u64 %0, t; }" : "=r"(a) : "l"(p));
  return a;
}
__device__ __forceinline__ float lrelu(float v) { return v >= 0.f ? v : 0.2f * v; }
__device__ __forceinline__ void red2(float* p, float x, float y) {
  asm volatile("red.global.add.v2.f32 [%0], {%1,%2};" :: "l"(p), "f"(x), "f"(y) : "memory");
}
__device__ __forceinline__ void red4(float* p, float4 v) {
  asm volatile("red.global.add.v4.f32 [%0], {%1,%2,%3,%4};"
               :: "l"(p), "f"(v.x), "f"(v.y), "f"(v.z), "f"(v.w) : "memory");
}
__device__ __forceinline__ void cpa16(uint32_t dst, const void* src) {
  asm volatile("cp.async.cg.shared.global [%0], [%1], 16;" :: "r"(dst), "l"(src));
}
#define CP_COMMIT() asm volatile("cp.async.commit_group;")
#define CP_WAIT0()  asm volatile("cp.async.wait_group 0;")

__device__ __forceinline__ uint32_t pack_h2(float a, float b) {
  __half2 h = __floats2half2_rn(a, b);
  return *reinterpret_cast<uint32_t*>(&h);
}

__device__ __forceinline__ void mma16(float* c, const uint32_t* a, uint32_t b0, uint32_t b1) {
  asm volatile(
      "mma.sync.aligned.m16n8k16.row.col.f32.f16.f16.f32 "
      "{%0,%1,%2,%3}, {%4,%5,%6,%7}, {%8,%9}, {%0,%1,%2,%3};\n"
      : "+f"(c[0]), "+f"(c[1]), "+f"(c[2]), "+f"(c[3])
      : "r"(a[0]), "r"(a[1]), "r"(a[2]), "r"(a[3]), "r"(b0), "r"(b1));
}
__device__ __forceinline__ void ldsm4(uint32_t* a, uint32_t addr) {
  asm volatile("ldmatrix.sync.aligned.m8n8.x4.shared.b16 {%0,%1,%2,%3}, [%4];"
               : "=r"(a[0]), "=r"(a[1]), "=r"(a[2]), "=r"(a[3]) : "r"(addr));
}

// A tile row: 136 halves (272 B/row; 16B-aligned, conflict-free LDSM/STS)
static constexpr int AS_RBYTES = 272;
static constexpr int AS_BYTES_128 = 128 * AS_RBYTES;  // 34816 (node tile)
static constexpr int AS_BYTES_64  = 64 * AS_RBYTES;   // 17408 (edge tile)

// MT = 16-row m-tiles per warp (2 -> 64-row tile, 4 -> 128-row tile)
template <int MT>
__device__ __forceinline__ void zero_acc(float acc[MT][4][4]) {
#pragma unroll
  for (int a = 0; a < MT; a++)
#pragma unroll
    for (int b = 0; b < 4; b++)
#pragma unroll
      for (int c = 0; c < 4; c++) acc[a][b][c] = 0.f;
}

// (MT*32)x128x128 fp16 chunk: acc += As @ Wchunk (B frags from gmem, L1-hit).
template <int MT>
__device__ __forceinline__ void gemm16t(uint32_t as_addr, const uint32_t* __restrict__ Wg,
                                        float acc[MT][4][4]) {
  const int lane = threadIdx.x & 31, warp = threadIdx.x >> 5;
  const int wm = warp >> 2, wn = warp & 3;
  const uint2* wb_base = reinterpret_cast<const uint2*>(Wg) + (wn * 4) * 32 + lane;
  const uint32_t abase =
      as_addr + (uint32_t)((wm * (MT * 16) + (lane & 15)) * AS_RBYTES + (lane >> 4) * 16);
#pragma unroll
  for (int ks = 0; ks < 8; ks++) {
    uint32_t a[MT][4];
#pragma unroll
    for (int mt = 0; mt < MT; mt++) ldsm4(a[mt], abase + mt * 16 * AS_RBYTES + ks * 32);
    const uint2* wb = wb_base + ks * 512;
#pragma unroll
    for (int nt = 0; nt < 4; nt++) {
      uint2 b = __ldg(wb + nt * 32);
#pragma unroll
      for (int mt = 0; mt < MT; mt++) mma16(acc[mt][nt], a[mt], b.x, b.y);
    }
  }
}

// acc + bias -> lrelu -> fp16 -> As (next layer's A operand).
template <int MT>
__device__ __forceinline__ void write_H16t(float acc[MT][4][4], const float* __restrict__ bias,
                                           char* __restrict__ smem) {
  const int lane = threadIdx.x & 31, warp = threadIdx.x >> 5;
  const int wm = warp >> 2, wn = warp & 3;
  const int g = lane >> 2, t = lane & 3;
#pragma unroll
  for (int nt = 0; nt < 4; nt++) {
    int col0 = wn * 32 + nt * 8 + 2 * t;
    float b0 = bias[col0], b1 = bias[col0 + 1];
#pragma unroll
    for (int mt = 0; mt < MT; mt++) {
      int r0 = wm * (MT * 16) + mt * 16 + g;
      *reinterpret_cast<uint32_t*>(smem + r0 * AS_RBYTES + col0 * 2) =
          pack_h2(lrelu(acc[mt][nt][0] + b0), lrelu(acc[mt][nt][1] + b1));
      *reinterpret_cast<uint32_t*>(smem + (r0 + 8) * AS_RBYTES + col0 * 2) =
          pack_h2(lrelu(acc[mt][nt][2] + b0), lrelu(acc[mt][nt][3] + b1));
    }
  }
}

// ---- 128-row staging (node kernel; 2 threads/row) ----------------------------
__device__ __forceinline__ void stage_cvt16_128(const float* __restrict__ base, int r0,
                                                int rmax, char* __restrict__ smem) {
  int t = threadIdx.x, row = t >> 1, half = t & 1;
  int rsrc = min(r0 + row, rmax - 1);
  const float* src = base + (size_t)rsrc * kM + half * 64;
  char* dst = smem + row * AS_RBYTES + half * 128;
#pragma unroll
  for (int q = 0; q < 8; q++) {
    float4 x = *reinterpret_cast<const float4*>(src + q * 8);
    float4 y = *reinterpret_cast<const float4*>(src + q * 8 + 4);
    *reinterpret_cast<uint4*>(dst + q * 16) =
        make_uint4(pack_h2(x.x, x.y), pack_h2(x.z, x.w), pack_h2(y.x, y.y), pack_h2(y.z, y.w));
  }
}

// ---- 64-row staging (edge kernel; 4 threads/row) ------------------------------
__device__ __forceinline__ void stage_gather16_64(const int* sidx, uint32_t as_addr) {
  int t = threadIdx.x, row = t >> 2, q = t & 3;
  const __half* src = g_atom_fp16 + (size_t)sidx[row] * kM + q * 32;
  uint32_t dst = as_addr + (uint32_t)(row * AS_RBYTES + q * 64);
#pragma unroll
  for (int k = 0; k < 4; k++) cpa16(dst + k * 16, src + k * 8);
}
__device__ __forceinline__ void stage_cvt16_64(const float* __restrict__ base, int r0,
                                               int rmax, char* __restrict__ smem) {
  int t = threadIdx.x, row = t >> 2, q = t & 3;
  int rsrc = min(r0 + row, rmax - 1);
  const float* src = base + (size_t)rsrc * kM + q * 32;
  char* dst = smem + row * AS_RBYTES + q * 64;
#pragma unroll
  for (int k = 0; k < 4; k++) {
    float4 x = *reinterpret_cast<const float4*>(src + k * 8);
    float4 y = *reinterpret_cast<const float4*>(src + k * 8 + 4);
    *reinterpret_cast<uint4*>(dst + k * 16) =
        make_uint4(pack_h2(x.x, x.y), pack_h2(x.z, x.w), pack_h2(y.x, y.y), pack_h2(y.z, y.w));
  }
}

// ---------------- kernel 1: setup --------------------------------------------
__global__ void setup_kernel(const float* __restrict__ atom,
                             const float* __restrict__ We1, const float* __restrict__ We2,
                             const float* __restrict__ We3,
                             const float* __restrict__ Wv1, const float* __restrict__ Wv2,
                             const float* __restrict__ Wv3,
                             float* __restrict__ out_glob) {
  int i = blockIdx.x * 256 + threadIdx.x;
  if (i < 1600000) {  // 6.4M floats as float4
    float4 z = make_float4(0.f, 0.f, 0.f, 0.f);
    reinterpret_cast<float4*>(g_rho)[i] = z;
    reinterpret_cast<float4*>(g_eksum)[i] = z;
    float4 a = reinterpret_cast<const float4*>(atom)[i];
    reinterpret_cast<uint2*>(g_atom_fp16)[i] =
        make_uint2(pack_h2(a.x, a.y), pack_h2(a.z, a.w));
  }
  if (i < 16384) reinterpret_cast<float4*>(out_glob)[i] = make_float4(0.f, 0.f, 0.f, 0.f);
  if (i < 32) {
    reinterpret_cast<float4*>(g_bnsum)[i] = make_float4(0.f, 0.f, 0.f, 0.f);
    reinterpret_cast<float4*>(g_bnsumsq)[i] = make_float4(0.f, 0.f, 0.f, 0.f);
  }
  if (i < 9 * 8192) {  // fp16 frag-major W images
    int c = i >> 13, r = i & 8191;
    int q = r & 1, l = (r >> 1) & 31, ntg = (r >> 6) & 15, ks = r >> 10;
    const float* Wc;
    if (c < 3)       Wc = We1 + c * 16384;
    else if (c == 3) Wc = We2;
    else if (c == 4) Wc = We3;
    else if (c < 7)  Wc = Wv1 + (c - 5) * 16384;
    else if (c == 7) Wc = Wv2;
    else             Wc = Wv3;
    int n = ntg * 8 + (l >> 2);
    int k0 = ks * 16 + 2 * (l & 3) + (q ? 8 : 0);
    g_Wfrag16[c * 8192 + r] = pack_h2(Wc[k0 * 128 + n], Wc[(k0 + 1) * 128 + n]);
  }
}

// ---------------- edge SMEM layout (64-row tile) ------------------------------
static constexpr int SM_IDX1 = AS_BYTES_64;        // 17408 (64 ints)
static constexpr int SM_IDX2 = SM_IDX1 + 256;
static constexpr int SM_INV  = SM_IDX2 + 256;
static constexpr int SM_BIAS = SM_INV + 256;       // 384 floats
static constexpr int EDGE_SMEM = SM_BIAS + 1536;   // 19712

// ---------------- kernel 2: edge MLP (64-row tiles, 3 CTAs/SM) ----------------
__global__ __launch_bounds__(256, 3) void edge_kernel(
    const float* __restrict__ nbr_fea, const float* __restrict__ num_nbrs,
    const int* __restrict__ idx1, const int* __restrict__ idx2,
    const float* __restrict__ be1, const float* __restrict__ be2,
    const float* __restrict__ be3, float* __restrict__ out_ek) {
  extern __shared__ char smem[];
  const uint32_t as_addr = smem_u32(smem);
  int* sidx1 = (int*)(smem + SM_IDX1);
  int* sidx2 = (int*)(smem + SM_IDX2);
  float* sinv = (float*)(smem + SM_INV);
  float* sbias = (float*)(smem + SM_BIAS);
  const int tid = threadIdx.x;
  const int e0 = blockIdx.x * 64;

  if (tid < 128) {
    sbias[tid] = be1[tid]; sbias[128 + tid] = be2[tid]; sbias[256 + tid] = be3[tid];
  }
  if (tid < 64) {
    int e = e0 + tid;
    int i1 = 0, i2 = 0;
    float inv = 0.f;
    if (e < kE) { i1 = idx1[e]; i2 = idx2[e]; inv = 1.f / num_nbrs[i1]; }
    sidx1[tid] = i1; sidx2[tid] = i2; sinv[tid] = inv;
  }
  __syncthreads();

  float acc[2][4][4];
  zero_acc<2>(acc);

  // Layer 1, chunk a1
  stage_gather16_64(sidx1, as_addr);
  CP_COMMIT(); CP_WAIT0();
  __syncthreads();
  gemm16t<2>(as_addr, g_Wfrag16, acc);
  __syncthreads();

  // chunk a2
  stage_gather16_64(sidx2, as_addr);
  CP_COMMIT(); CP_WAIT0();
  __syncthreads();
  gemm16t<2>(as_addr, g_Wfrag16 + 8192, acc);
  __syncthreads();

  // chunk nbr
  stage_cvt16_64(nbr_fea, e0, kE, smem);
  __syncthreads();
  gemm16t<2>(as_addr, g_Wfrag16 + 2 * 8192, acc);
  __syncthreads();

  // layer 2
  write_H16t<2>(acc, sbias, smem);
  __syncthreads();
  zero_acc<2>(acc);
  gemm16t<2>(as_addr, g_Wfrag16 + 3 * 8192, acc);
  __syncthreads();

  // layer 3
  write_H16t<2>(acc, sbias + 128, smem);
  __syncthreads();
  zero_acc<2>(acc);
  gemm16t<2>(as_addr, g_Wfrag16 + 4 * 8192, acc);

  // Epilogue (R10 proven form): ek = nbr + ek_raw; red2 into rho/eksum.
  const int lane = tid & 31, warp = tid >> 5;
  const int wm = warp >> 2, wn = warp & 3;
  const int g = lane >> 2, t = lane & 3;
#pragma unroll
  for (int mt = 0; mt < 2; mt++) {
#pragma unroll
    for (int h = 0; h < 2; h++) {
      int row = wm * 32 + mt * 16 + g + h * 8;
      int e = e0 + row;
      if (e < kE) {
        float inv = sinv[row];
        size_t nbase = (size_t)sidx1[row] * kM;
        const float* nrow = nbr_fea + (size_t)e * kM;
        float* eko = out_ek + (size_t)e * kM;
#pragma unroll
        for (int nt = 0; nt < 4; nt++) {
          int col0 = wn * 32 + nt * 8 + 2 * t;
          float ek0 = acc[mt][nt][2 * h]     + sbias[256 + col0];
          float ek1 = acc[mt][nt][2 * h + 1] + sbias[256 + col0 + 1];
          float2 nb = *reinterpret_cast<const float2*>(nrow + col0);
          float o0 = ek0 + nb.x, o1 = ek1 + nb.y;
          *reinterpret_cast<float2*>(eko + col0) = make_float2(o0, o1);
          red2(g_rho + nbase + col0, ek0 * inv, ek1 * inv);
          red2(g_eksum + nbase + col0, o0 * inv, o1 * inv);
        }
      }
    }
  }
}

// ---------------- kernel 3: node MLP (R10 proven 128-row form) ----------------
__global__ __launch_bounds__(256, 2) void node_kernel(
    const float* __restrict__ bv1, const float* __restrict__ bv2,
    const float* __restrict__ bv3) {
  extern __shared__ char smem[];
  const uint32_t as_addr = smem_u32(smem);
  const int tid = threadIdx.x;
  const int n0 = blockIdx.x * 128;

  float acc[4][4][4];
  zero_acc<4>(acc);

  // chunk atom (cp.async, contiguous fp16 rows; clamp last block)
  {
    int row = tid >> 1, half = tid & 1;
    int rsrc = min(n0 + row, kN - 1);
    const __half* src = g_atom_fp16 + (size_t)rsrc * kM + half * 64;
    uint32_t dst = as_addr + (uint32_t)(row * AS_RBYTES + half * 128);
#pragma unroll
    for (int q = 0; q < 8; q++) cpa16(dst + q * 16, src + q * 8);
    CP_COMMIT(); CP_WAIT0();
  }
  __syncthreads();
  gemm16t<4>(as_addr, g_Wfrag16 + 5 * 8192, acc);
  __syncthreads();

  // chunk rho
  stage_cvt16_128(g_rho, n0, kN, smem);
  __syncthreads();
  gemm16t<4>(as_addr, g_Wfrag16 + 6 * 8192, acc);
  __syncthreads();

  write_H16t<4>(acc, bv1, smem);
  __syncthreads();
  zero_acc<4>(acc);
  gemm16t<4>(as_addr, g_Wfrag16 + 7 * 8192, acc);
  __syncthreads();

  write_H16t<4>(acc, bv2, smem);
  __syncthreads();
  zero_acc<4>(acc);
  gemm16t<4>(as_addr, g_Wfrag16 + 8 * 8192, acc);

  // Epilogue: vi_raw -> gmem + BN partials (warp shfl-reduce, red2).
  const int lane = tid & 31, warp = tid >> 5;
  const int wm = warp >> 2, wn = warp & 3;
  const int g = lane >> 2, t = lane & 3;
#pragma unroll
  for (int nt = 0; nt < 4; nt++) {
    int col0 = wn * 32 + nt * 8 + 2 * t;
    float b0 = bv3[col0], b1 = bv3[col0 + 1];
    float s0 = 0.f, s1 = 0.f, q0 = 0.f, q1 = 0.f;
#pragma unroll
    for (int mt = 0; mt < 4; mt++) {
#pragma unroll
      for (int h = 0; h < 2; h++) {
        int r = wm * 64 + mt * 16 + g + h * 8;
        float v0 = acc[mt][nt][2 * h] + b0;
        float v1 = acc[mt][nt][2 * h + 1] + b1;
        if (n0 + r < kN) {
          *reinterpret_cast<float2*>(g_viraw + (size_t)(n0 + r) * kM + col0) =
              make_float2(v0, v1);
          s0 += v0; s1 += v1;
          q0 += v0 * v0; q1 += v1 * v1;
        }
      }
    }
#pragma unroll
    for (int o = 4; o < 32; o <<= 1) {
      s0 += __shfl_xor_sync(0xFFFFFFFF, s0, o);
      s1 += __shfl_xor_sync(0xFFFFFFFF, s1, o);
      q0 += __shfl_xor_sync(0xFFFFFFFF, q0, o);
      q1 += __shfl_xor_sync(0xFFFFFFFF, q1, o);
    }
    if (lane < 4) {
      red2(g_bnsum + col0, s0, s1);
      red2(g_bnsumsq + col0, q0, q1);
    }
  }
}

// ---------------- kernel 4: apply (BN finalize folded in) ---------------------
__global__ __launch_bounds__(256) void apply_kernel(
    const float* __restrict__ atom, const int* __restrict__ crys,
    const float* __restrict__ gamma, const float* __restrict__ beta,
    float* __restrict__ out_vi, float* __restrict__ out_glob,
    float* __restrict__ out_anf) {
  __shared__ float ssc[kM], ssh[kM];
  if (threadIdx.x < kM) {
    int t = threadIdx.x;
    float mu = g_bnsum[t] * (1.f / (float)kN);
    float var = g_bnsumsq[t] * (1.f / (float)kN) - mu * mu;
    float sc = gamma[t] * rsqrtf(var + 1e-5f);
    ssc[t] = sc;
    ssh[t] = beta[t] - mu * sc;
  }
  __syncthreads();
  int i = blockIdx.x * blockDim.x + threadIdx.x;
  if (i >= kN * 32) return;
  int n = i >> 5, j0 = (i & 31) << 2;
  float4 a = *reinterpret_cast<const float4*>(atom + (size_t)n * kM + j0);
  float4 vr = *reinterpret_cast<const float4*>(g_viraw + (size_t)n * kM + j0);
  float4 v;
  v.x = a.x + vr.x * ssc[j0] + ssh[j0];
  v.y = a.y + vr.y * ssc[j0 + 1] + ssh[j0 + 1];
  v.z = a.z + vr.z * ssc[j0 + 2] + ssh[j0 + 2];
  v.w = a.w + vr.w * ssc[j0 + 3] + ssh[j0 + 3];
  float4 ekv = *reinterpret_cast<const float4*>(g_eksum + (size_t)n * kM + j0);

  *reinterpret_cast<float4*>(out_vi + (size_t)n * kM + j0) = v;
  *reinterpret_cast<float4*>(out_anf + (size_t)n * 256 + j0) = v;
  *reinterpret_cast<float4*>(out_anf + (size_t)n * 256 + 128 + j0) = ekv;
  int cr = crys[n];
  red4(out_glob + (size_t)cr * 256 + j0, v);
  red4(out_glob + (size_t)cr * 256 + 128 + j0, ekv);
}

// ---------------- launcher ----------------------------------------------------
extern "C" void kernel_launch(void* const* d_in, const int* in_sizes, int n_in,
                              void* d_out, int out_size) {
  const float* atom     = (const float*)d_in[0];
  const float* nbr_fea  = (const float*)d_in[1];
  const float* num_nbrs = (const float*)d_in[2];
  const int*   idx1     = (const int*)d_in[3];
  const int*   idx2     = (const int*)d_in[4];
  const int*   crys     = (const int*)d_in[5];
  const float* We1 = (const float*)d_in[6];
  const float* be1 = (const float*)d_in[7];
  const float* We2 = (const float*)d_in[8];
  const float* be2 = (const float*)d_in[9];
  const float* We3 = (const float*)d_in[10];
  const float* be3 = (const float*)d_in[11];
  const float* Wv1 = (const float*)d_in[12];
  const float* bv1 = (const float*)d_in[13];
  const float* Wv2 = (const float*)d_in[14];
  const float* bv2 = (const float*)d_in[15];
  const float* Wv3 = (const float*)d_in[16];
  const float* bv3 = (const float*)d_in[17];
  const float* bn_gamma = (const float*)d_in[18];
  const float* bn_beta  = (const float*)d_in[19];

  float* out = (float*)d_out;
  float* out_ek   = out;
  float* out_vi   = out + OFF_VI;
  float* out_glob = out + OFF_GLOB;
  float* out_anf  = out + OFF_ANF;

  static const int NODE_SMEM = AS_BYTES_128 + 1024;  // 35840
  cudaFuncSetAttribute(edge_kernel, cudaFuncAttributeMaxDynamicSharedMemorySize, EDGE_SMEM);
  cudaFuncSetAttribute(node_kernel, cudaFuncAttributeMaxDynamicSharedMemorySize, NODE_SMEM);

  setup_kernel<<<6250, 256>>>(atom, We1, We2, We3, Wv1, Wv2, Wv3, out_glob);
  edge_kernel<<<(kE + 63) / 64, 256, EDGE_SMEM>>>(
      nbr_fea, num_nbrs, idx1, idx2, be1, be2, be3, out_ek);
  node_kernel<<<(kN + 127) / 128, 256, NODE_SMEM>>>(bv1, bv2, bv3);
  apply_kernel<<<(kN * 32 + 255) / 256, 256>>>(
      atom, crys, bn_gamma, bn_beta, out_vi, out_glob, out_anf);
}